// round 1
// baseline (speedup 1.0000x reference)
#include <cuda_runtime.h>
#include <cuda_bf16.h>
#include <cstdint>

// AlSalamCarlitzKANLayer: y[b,o] = sum_{i,d} P_d(tanh(x[b,i])) * coeffs[i,o,d]
// B=4096, I=1024, O=1024, D+1=8  ->  GEMM M=4096, N=1024, K=8192 with A generated on the fly.
//
// Baseline: SIMT fp32 GEMM using packed fma.rn.f32x2 (Blackwell FFMA2, 2x fp32 rate).

#define BATCH   4096
#define IN_DIM  1024
#define OUT_DIM 1024
#define NB      8      // degree + 1

#define BM 128
#define BN 128
#define BKI 4          // i-values per tile iteration
#define KK (BKI * NB)  // 32 k-slices per iteration
#define TM 8
#define TN 8
#define THREADS 256

__device__ __forceinline__ uint64_t dup_f32x2(float v) {
    uint64_t r;
    uint32_t b = __float_as_uint(v);
    asm("mov.b64 %0, {%1, %1};" : "=l"(r) : "r"(b));
    return r;
}

__device__ __forceinline__ void ffma2(uint64_t& acc, uint64_t a, uint64_t b) {
    asm("fma.rn.f32x2 %0, %1, %2, %0;" : "+l"(acc) : "l"(a), "l"(b));
}

__global__ __launch_bounds__(THREADS)
void kan_gemm_kernel(const float* __restrict__ x,
                     const float* __restrict__ a_ptr,
                     const float* __restrict__ q_ptr,
                     const float* __restrict__ coeffs,
                     float* __restrict__ y) {
    __shared__ float As[KK][BM];  // 32 x 128 x 4B = 16 KB, [k][m]
    __shared__ float Bs[KK][BN];  // 16 KB, [k][n]

    const float a = a_ptr[0];
    const float q = q_ptr[0];

    const int bn0 = blockIdx.x * BN;
    const int bm0 = blockIdx.y * BM;
    const int tid = threadIdx.x;

    const int tm0 = (tid / 16) * TM;  // 16 groups of 8 rows
    const int tn0 = (tid % 16) * TN;  // 16 groups of 8 cols

    // Packed accumulators: acc2[j][n] holds (row tm0+2j, row tm0+2j+1) x col tn0+n
    uint64_t acc2[TM / 2][TN];
#pragma unroll
    for (int j = 0; j < TM / 2; j++)
#pragma unroll
        for (int n = 0; n < TN; n++) acc2[j][n] = 0ull;

    for (int i0 = 0; i0 < IN_DIM; i0 += BKI) {
        // ---- Load coeffs tile into Bs: coeffs[i0+c, bn0:bn0+BN, 0:8] is contiguous per c ----
        // Total floats = BKI*BN*NB = 4096 -> 1024 float4, 4 per thread.
#pragma unroll
        for (int jj = 0; jj < 4; jj++) {
            int t = tid + jj * THREADS;      // 0..1023
            int chunk = t >> 8;              // i-local 0..3
            int f = t & 255;                 // float4 index within chunk (256 per chunk)
            const float4 v = *reinterpret_cast<const float4*>(
                coeffs + (size_t)(i0 + chunk) * (OUT_DIM * NB) + (size_t)bn0 * NB + (size_t)f * 4);
            int n = f >> 1;                  // local o
            int d4 = (f & 1) * 4;            // d group 0..3 or 4..7
            int kr = chunk * NB + d4;
            Bs[kr + 0][n] = v.x;
            Bs[kr + 1][n] = v.y;
            Bs[kr + 2][n] = v.z;
            Bs[kr + 3][n] = v.w;
        }

        // ---- Load x, compute tanh + basis recurrence, write As[k][m] ----
        // 512 elements (128 rows x 4 i), 2 per thread.
#pragma unroll
        for (int jj = 0; jj < 2; jj++) {
            int e = tid + jj * THREADS;      // 0..511
            int il = e >> 7;                 // i-local 0..3
            int row = e & 127;
            float xv = x[(size_t)(bm0 + row) * IN_DIM + i0 + il];
            float xt = tanhf(xv);
            float p0 = 1.0f;
            float p1 = xt - a;
            As[il * NB + 0][row] = p0;
            As[il * NB + 1][row] = p1;
            float qn = q;  // q^(n-1)
#pragma unroll
            for (int n = 2; n < NB; n++) {
                float qn1 = qn * q;  // q^n
                float pn = (xt - (a + qn1)) * p1 - (a * qn) * p0;
                As[il * NB + n][row] = pn;
                p0 = p1;
                p1 = pn;
                qn = qn1;
            }
        }

        __syncthreads();

        // ---- Inner product over 32 k-slices ----
#pragma unroll
        for (int k = 0; k < KK; k++) {
            // A pairs: consecutive rows already adjacent in memory -> free f32x2 packing
            uint64_t ap[TM / 2];
#pragma unroll
            for (int j = 0; j < TM / 2; j++)
                ap[j] = *reinterpret_cast<const uint64_t*>(&As[k][tm0 + 2 * j]);

            float bvf[TN];
            *reinterpret_cast<float4*>(&bvf[0]) = *reinterpret_cast<const float4*>(&Bs[k][tn0]);
            *reinterpret_cast<float4*>(&bvf[4]) = *reinterpret_cast<const float4*>(&Bs[k][tn0 + 4]);

#pragma unroll
            for (int n = 0; n < TN; n++) {
                uint64_t bd = dup_f32x2(bvf[n]);
#pragma unroll
                for (int j = 0; j < TM / 2; j++) ffma2(acc2[j][n], ap[j], bd);
            }
        }

        __syncthreads();
    }

    // ---- Epilogue: unpack packed accumulators, store coalesced float4 ----
#pragma unroll
    for (int j = 0; j < TM / 2; j++) {
        float lo[TN], hi[TN];
#pragma unroll
        for (int n = 0; n < TN; n++) {
            lo[n] = __uint_as_float((uint32_t)(acc2[j][n] & 0xFFFFFFFFull));
            hi[n] = __uint_as_float((uint32_t)(acc2[j][n] >> 32));
        }
        size_t r0 = (size_t)(bm0 + tm0 + 2 * j) * OUT_DIM + bn0 + tn0;
        size_t r1 = r0 + OUT_DIM;
        *reinterpret_cast<float4*>(y + r0)     = make_float4(lo[0], lo[1], lo[2], lo[3]);
        *reinterpret_cast<float4*>(y + r0 + 4) = make_float4(lo[4], lo[5], lo[6], lo[7]);
        *reinterpret_cast<float4*>(y + r1)     = make_float4(hi[0], hi[1], hi[2], hi[3]);
        *reinterpret_cast<float4*>(y + r1 + 4) = make_float4(hi[4], hi[5], hi[6], hi[7]);
    }
}

extern "C" void kernel_launch(void* const* d_in, const int* in_sizes, int n_in,
                              void* d_out, int out_size) {
    const float* x      = (const float*)d_in[0];  // [4096, 1024]
    const float* a_ptr  = (const float*)d_in[1];  // [1]
    const float* q_ptr  = (const float*)d_in[2];  // [1]
    const float* coeffs = (const float*)d_in[3];  // [1024, 1024, 8]
    float* y = (float*)d_out;                     // [4096, 1024]

    dim3 grid(OUT_DIM / BN, BATCH / BM);  // (8, 32)
    kan_gemm_kernel<<<grid, THREADS>>>(x, a_ptr, q_ptr, coeffs, y);
}

// round 2
// speedup vs baseline: 1.2935x; 1.2935x over previous
#include <cuda_runtime.h>
#include <cuda_bf16.h>
#include <cstdint>

// y[b,o] = sum_{i,d} P_d(tanh(x[b,i])) * coeffs[i,o,d]
// GEMM M=4096 N=1024 K=8192, A generated on the fly.
// Tensor-core path: mma.sync.m16n8k16 bf16, split-bf16 (hi/lo) 3-pass for fp32-like accuracy.

#define BATCH   4096
#define IN_DIM  1024
#define OUT_DIM 1024
#define NB      8

#define BM 128
#define BN 128
#define BKI 4          // i per tile iter
#define KK (BKI * NB)  // 32 k-slices per iter
#define THREADS 512    // 16 warps, 4x4 warp grid, warp tile 32x32

#define A_LD 40        // bf16 elems per row (80B stride: 16B-aligned, conflict-free)
#define B_LD 136       // bf16 elems per row (272B stride: 16B-aligned, conflict-free)

__device__ __forceinline__ void ldmatrix_x4(uint32_t& r0, uint32_t& r1, uint32_t& r2, uint32_t& r3,
                                            uint32_t addr) {
    asm volatile("ldmatrix.sync.aligned.m8n8.x4.shared.b16 {%0,%1,%2,%3}, [%4];"
                 : "=r"(r0), "=r"(r1), "=r"(r2), "=r"(r3) : "r"(addr));
}
__device__ __forceinline__ void ldmatrix_x4_trans(uint32_t& r0, uint32_t& r1, uint32_t& r2, uint32_t& r3,
                                                  uint32_t addr) {
    asm volatile("ldmatrix.sync.aligned.m8n8.x4.trans.shared.b16 {%0,%1,%2,%3}, [%4];"
                 : "=r"(r0), "=r"(r1), "=r"(r2), "=r"(r3) : "r"(addr));
}
__device__ __forceinline__ void mma16816(float* d, const uint32_t* a, uint32_t b0, uint32_t b1) {
    asm volatile("mma.sync.aligned.m16n8k16.row.col.f32.bf16.bf16.f32 "
                 "{%0,%1,%2,%3}, {%4,%5,%6,%7}, {%8,%9}, {%0,%1,%2,%3};"
                 : "+f"(d[0]), "+f"(d[1]), "+f"(d[2]), "+f"(d[3])
                 : "r"(a[0]), "r"(a[1]), "r"(a[2]), "r"(a[3]), "r"(b0), "r"(b1));
}

__device__ __forceinline__ uint32_t pack_bf16x2(__nv_bfloat16 lo, __nv_bfloat16 hi) {
    uint32_t r = ((uint32_t)__bfloat16_as_ushort(hi) << 16) | (uint32_t)__bfloat16_as_ushort(lo);
    return r;
}

__global__ __launch_bounds__(THREADS)
void kan_mma_kernel(const float* __restrict__ x,
                    const float* __restrict__ a_ptr,
                    const float* __restrict__ q_ptr,
                    const float* __restrict__ coeffs,
                    float* __restrict__ y) {
    __shared__ __align__(16) __nv_bfloat16 Ah[BM][A_LD];
    __shared__ __align__(16) __nv_bfloat16 Al[BM][A_LD];
    __shared__ __align__(16) __nv_bfloat16 Bh[KK][B_LD];
    __shared__ __align__(16) __nv_bfloat16 Bl[KK][B_LD];

    const float a = a_ptr[0];
    const float q = q_ptr[0];

    const int bn0 = blockIdx.x * BN;
    const int bm0 = blockIdx.y * BM;
    const int tid = threadIdx.x;
    const int lane = tid & 31;
    const int warp = tid >> 5;
    const int wm = warp >> 2;   // 0..3
    const int wn = warp & 3;    // 0..3

    float acc[2][4][4];
#pragma unroll
    for (int mi = 0; mi < 2; mi++)
#pragma unroll
        for (int ng = 0; ng < 4; ng++)
#pragma unroll
            for (int r = 0; r < 4; r++) acc[mi][ng][r] = 0.0f;

    // ldmatrix base addresses (per-lane, computed once)
    const uint32_t sAh = (uint32_t)__cvta_generic_to_shared(&Ah[0][0]);
    const uint32_t sAl = (uint32_t)__cvta_generic_to_shared(&Al[0][0]);
    const uint32_t sBh = (uint32_t)__cvta_generic_to_shared(&Bh[0][0]);
    const uint32_t sBl = (uint32_t)__cvta_generic_to_shared(&Bl[0][0]);
    const int arow = wm * 32 + (lane & 15);      // + mi*16
    const int acol = (lane >> 4) * 8;            // + ks*16
    const int brow = (lane & 15);                // + ks*16
    const int bcol = wn * 32 + (lane >> 4) * 8;  // + ngg*16

    // ---- tile loaders ----
    float4 pfB[2];
    float pfX;
    // B prefetch indices (constant across iters)
    // t = tid + jj*512 in 0..1023: chunk=i-local (t>>8), f = float4 idx in chunk (t&255)

    auto loadG = [&](int i0) {
#pragma unroll
        for (int jj = 0; jj < 2; jj++) {
            int t = tid + jj * THREADS;
            int chunk = t >> 8;
            int f = t & 255;
            pfB[jj] = *reinterpret_cast<const float4*>(
                coeffs + (size_t)(i0 + chunk) * (OUT_DIM * NB) + (size_t)bn0 * NB + (size_t)f * 4);
        }
        int il = tid & 3;
        int row = tid >> 2;
        pfX = x[(size_t)(bm0 + row) * IN_DIM + i0 + il];
    };

    auto storeS = [&]() {
        // ---- B: split fp32 -> bf16 hi/lo, scatter into [k][n] ----
#pragma unroll
        for (int jj = 0; jj < 2; jj++) {
            int t = tid + jj * THREADS;
            int chunk = t >> 8;
            int f = t & 255;
            int n = f >> 1;
            int d4 = (f & 1) * 4;
            int kr = chunk * NB + d4;
            float v[4] = {pfB[jj].x, pfB[jj].y, pfB[jj].z, pfB[jj].w};
#pragma unroll
            for (int j = 0; j < 4; j++) {
                __nv_bfloat16 h = __float2bfloat16(v[j]);
                __nv_bfloat16 l = __float2bfloat16(v[j] - __bfloat162float(h));
                Bh[kr + j][n] = h;
                Bl[kr + j][n] = l;
            }
        }
        // ---- A: tanh + recurrence, split, vectorized 16B store ----
        {
            int il = tid & 3;
            int row = tid >> 2;
            float xt = tanhf(pfX);
            float p[NB];
            p[0] = 1.0f;
            p[1] = xt - a;
            float qn = q;
#pragma unroll
            for (int n = 2; n < NB; n++) {
                float qn1 = qn * q;
                p[n] = (xt - (a + qn1)) * p[n - 1] - (a * qn) * p[n - 2];
                qn = qn1;
            }
            uint32_t hw[4], lw[4];
#pragma unroll
            for (int j = 0; j < 4; j++) {
                __nv_bfloat16 h0 = __float2bfloat16(p[2 * j]);
                __nv_bfloat16 h1 = __float2bfloat16(p[2 * j + 1]);
                __nv_bfloat16 l0 = __float2bfloat16(p[2 * j] - __bfloat162float(h0));
                __nv_bfloat16 l1 = __float2bfloat16(p[2 * j + 1] - __bfloat162float(h1));
                hw[j] = pack_bf16x2(h0, h1);
                lw[j] = pack_bf16x2(l0, l1);
            }
            *reinterpret_cast<uint4*>(&Ah[row][il * NB]) = make_uint4(hw[0], hw[1], hw[2], hw[3]);
            *reinterpret_cast<uint4*>(&Al[row][il * NB]) = make_uint4(lw[0], lw[1], lw[2], lw[3]);
        }
    };

    auto compute = [&]() {
#pragma unroll
        for (int ks = 0; ks < 2; ks++) {
            uint32_t ah[2][4], al[2][4];
#pragma unroll
            for (int mi = 0; mi < 2; mi++) {
                uint32_t off = (uint32_t)((arow + mi * 16) * A_LD + ks * 16 + acol) * 2u;
                ldmatrix_x4(ah[mi][0], ah[mi][1], ah[mi][2], ah[mi][3], sAh + off);
                ldmatrix_x4(al[mi][0], al[mi][1], al[mi][2], al[mi][3], sAl + off);
            }
#pragma unroll
            for (int ngg = 0; ngg < 2; ngg++) {
                uint32_t bh[4], bl[4];
                uint32_t off = (uint32_t)((ks * 16 + brow) * B_LD + bcol + ngg * 16) * 2u;
                ldmatrix_x4_trans(bh[0], bh[1], bh[2], bh[3], sBh + off);
                ldmatrix_x4_trans(bl[0], bl[1], bl[2], bl[3], sBl + off);
#pragma unroll
                for (int mi = 0; mi < 2; mi++) {
                    mma16816(acc[mi][2 * ngg],     ah[mi], bh[0], bh[1]);
                    mma16816(acc[mi][2 * ngg + 1], ah[mi], bh[2], bh[3]);
                    mma16816(acc[mi][2 * ngg],     ah[mi], bl[0], bl[1]);
                    mma16816(acc[mi][2 * ngg + 1], ah[mi], bl[2], bl[3]);
                    mma16816(acc[mi][2 * ngg],     al[mi], bh[0], bh[1]);
                    mma16816(acc[mi][2 * ngg + 1], al[mi], bh[2], bh[3]);
                }
            }
        }
    };

    // ---- pipeline: load(i) overlaps compute(i-1) ----
    loadG(0);
    storeS();
    __syncthreads();
    for (int i0 = BKI; i0 < IN_DIM; i0 += BKI) {
        loadG(i0);
        compute();
        __syncthreads();   // all warps done reading current tile
        storeS();
        __syncthreads();   // new tile visible
    }
    compute();

    // ---- epilogue ----
#pragma unroll
    for (int mi = 0; mi < 2; mi++) {
#pragma unroll
        for (int ng = 0; ng < 4; ng++) {
            int r = bm0 + wm * 32 + mi * 16 + (lane >> 2);
            int c = bn0 + wn * 32 + ng * 8 + (lane & 3) * 2;
            *reinterpret_cast<float2*>(y + (size_t)r * OUT_DIM + c) =
                make_float2(acc[mi][ng][0], acc[mi][ng][1]);
            *reinterpret_cast<float2*>(y + (size_t)(r + 8) * OUT_DIM + c) =
                make_float2(acc[mi][ng][2], acc[mi][ng][3]);
        }
    }
}

extern "C" void kernel_launch(void* const* d_in, const int* in_sizes, int n_in,
                              void* d_out, int out_size) {
    const float* x      = (const float*)d_in[0];
    const float* a_ptr  = (const float*)d_in[1];
    const float* q_ptr  = (const float*)d_in[2];
    const float* coeffs = (const float*)d_in[3];
    float* y = (float*)d_out;

    dim3 grid(OUT_DIM / BN, BATCH / BM);  // (8, 32)
    kan_mma_kernel<<<grid, THREADS>>>(x, a_ptr, q_ptr, coeffs, y);
}

// round 4
// speedup vs baseline: 2.6634x; 2.0591x over previous
#include <cuda_runtime.h>
#include <cuda_bf16.h>
#include <cstdint>

// y[b,o] = sum_{i,d} P_d(tanh(x[b,i])) * coeffs[i,o,d]
// GEMM M=4096 N=1024 K=8192, A generated on the fly.
// mma.sync m16n8k16 bf16, split-bf16 3-pass (AhBh + AhBl + AlBh), fp32 accum.
// v4: 128x256 CTA (1 wave), 64x64 warp tiles, double-buffered smem, reg-prefetch.

#define BATCH   4096
#define IN_DIM  1024
#define OUT_DIM 1024
#define NB      8

#define BM 128
#define BN 256
#define BKI 4                  // i-values per iter
#define KK  32                 // k per iter
#define NIT (IN_DIM / BKI)     // 256
#define THREADS 256            // 8 warps, warp grid 2(M) x 4(N), warp tile 64x64

#define A_LD 40                // bf16 per row (80B stride, conflict-free, 16B aligned)
#define B_LD 40
#define A_BYTES (BM * A_LD * 2)            // 10240
#define B_BYTES (BN * B_LD * 2)            // 20480
#define BUF_BYTES (2 * A_BYTES + 2 * B_BYTES)  // 61440: Ah, Al, Bh, Bl
#define SMEM_DYN (2 * BUF_BYTES)               // 122880

__device__ __forceinline__ void ldx4(uint32_t* r, uint32_t addr) {
    asm volatile("ldmatrix.sync.aligned.m8n8.x4.shared.b16 {%0,%1,%2,%3}, [%4];"
                 : "=r"(r[0]), "=r"(r[1]), "=r"(r[2]), "=r"(r[3]) : "r"(addr));
}
__device__ __forceinline__ void mma16816(float* d, const uint32_t* a, uint32_t b0, uint32_t b1) {
    asm volatile("mma.sync.aligned.m16n8k16.row.col.f32.bf16.bf16.f32 "
                 "{%0,%1,%2,%3}, {%4,%5,%6,%7}, {%8,%9}, {%0,%1,%2,%3};"
                 : "+f"(d[0]), "+f"(d[1]), "+f"(d[2]), "+f"(d[3])
                 : "r"(a[0]), "r"(a[1]), "r"(a[2]), "r"(a[3]), "r"(b0), "r"(b1));
}
__device__ __forceinline__ uint32_t bf2u(__nv_bfloat162 v) {
    return *reinterpret_cast<uint32_t*>(&v);
}

__global__ __launch_bounds__(THREADS, 1)
void kan_mma2_kernel(const float* __restrict__ x,
                     const float* __restrict__ a_ptr,
                     const float* __restrict__ q_ptr,
                     const float* __restrict__ coeffs,
                     float* __restrict__ y) {
    extern __shared__ __align__(16) char sm[];
    const uint32_t sbase = (uint32_t)__cvta_generic_to_shared(sm);

    const float a = a_ptr[0];
    const float q = q_ptr[0];
    const int bn0 = blockIdx.x * BN;
    const int bm0 = blockIdx.y * BM;
    const int tid = threadIdx.x;
    const int lane = tid & 31;
    const int warp = tid >> 5;
    const int wm = warp >> 2;   // 0..1
    const int wn = warp & 3;    // 0..3

    // accumulators: [mi 0..3][n8 0..7][4]
    float acc[4][8][4];
#pragma unroll
    for (int mi = 0; mi < 4; mi++)
#pragma unroll
        for (int nb = 0; nb < 8; nb++)
#pragma unroll
            for (int r = 0; r < 4; r++) acc[mi][nb][r] = 0.0f;

    // ldmatrix lane offsets
    const int aRow = wm * 64 + (lane & 15);                    // + mi*16
    const int aCol = (lane >> 4) * 8;                          // + ks*16
    const uint32_t aOff = (uint32_t)(aRow * A_LD + aCol) * 2u;
    const int bRow = wn * 64 + ((lane >> 4) << 3) + (lane & 7);  // + ng*16
    const int bCol = ((lane >> 3) & 1) * 8;                      // + ks*16
    const uint32_t bOff = (uint32_t)(bRow * B_LD + bCol) * 2u;

    // register prefetch
    float4 pfB[8];
    float pfX[2];

    auto loadG = [&](int i0) {
#pragma unroll
        for (int jj = 0; jj < 8; jj++) {
            int t = tid + jj * THREADS;   // 0..2047
            int il = t >> 9;              // 0..3
            int f = t & 511;              // n = f>>1, dh = f&1
            int n = f >> 1;
            int dh = f & 1;
            pfB[jj] = *reinterpret_cast<const float4*>(
                coeffs + (size_t)(i0 + il) * (OUT_DIM * NB) + (size_t)(bn0 + n) * NB + dh * 4);
        }
#pragma unroll
        for (int jj = 0; jj < 2; jj++) {
            int e = tid + jj * THREADS;   // 0..511
            int il = e & 3;
            int row = e >> 2;
            pfX[jj] = x[(size_t)(bm0 + row) * IN_DIM + i0 + il];
        }
    };

    auto storeS = [&](int buf) {
        char* const base = sm + buf * BUF_BYTES;
        char* const Ah = base;
        char* const Al = base + A_BYTES;
        char* const Bh = base + 2 * A_BYTES;
        char* const Bl = base + 2 * A_BYTES + B_BYTES;

        // B: [n][k] layout, k = il*8 + d (d contiguous)
#pragma unroll
        for (int jj = 0; jj < 8; jj++) {
            int t = tid + jj * THREADS;
            int il = t >> 9;
            int f = t & 511;
            int n = f >> 1;
            int dh = f & 1;
            float v[4] = {pfB[jj].x, pfB[jj].y, pfB[jj].z, pfB[jj].w};
            __nv_bfloat162 h01 = __floats2bfloat162_rn(v[0], v[1]);
            __nv_bfloat162 h23 = __floats2bfloat162_rn(v[2], v[3]);
            __nv_bfloat162 l01 = __floats2bfloat162_rn(v[0] - __bfloat162float(h01.x),
                                                       v[1] - __bfloat162float(h01.y));
            __nv_bfloat162 l23 = __floats2bfloat162_rn(v[2] - __bfloat162float(h23.x),
                                                       v[3] - __bfloat162float(h23.y));
            uint32_t off = (uint32_t)(n * B_LD + il * 8 + dh * 4) * 2u;
            *reinterpret_cast<uint2*>(Bh + off) = make_uint2(bf2u(h01), bf2u(h23));
            *reinterpret_cast<uint2*>(Bl + off) = make_uint2(bf2u(l01), bf2u(l23));
        }

        // A: [m][k] layout, k = il*8 + d
#pragma unroll
        for (int jj = 0; jj < 2; jj++) {
            int e = tid + jj * THREADS;
            int il = e & 3;
            int row = e >> 2;
            float xt = tanhf(pfX[jj]);
            float p[NB];
            p[0] = 1.0f;
            p[1] = xt - a;
            float qn = q;
#pragma unroll
            for (int n = 2; n < NB; n++) {
                float qn1 = qn * q;
                p[n] = (xt - (a + qn1)) * p[n - 1] - (a * qn) * p[n - 2];
                qn = qn1;
            }
            uint32_t hw[4], lw[4];
#pragma unroll
            for (int j = 0; j < 4; j++) {
                __nv_bfloat162 h = __floats2bfloat162_rn(p[2 * j], p[2 * j + 1]);
                __nv_bfloat162 l = __floats2bfloat162_rn(p[2 * j]     - __bfloat162float(h.x),
                                                         p[2 * j + 1] - __bfloat162float(h.y));
                hw[j] = bf2u(h);
                lw[j] = bf2u(l);
            }
            uint32_t off = (uint32_t)(row * A_LD + il * 8) * 2u;
            *reinterpret_cast<uint4*>(Ah + off) = make_uint4(hw[0], hw[1], hw[2], hw[3]);
            *reinterpret_cast<uint4*>(Al + off) = make_uint4(lw[0], lw[1], lw[2], lw[3]);
        }
    };

    auto compute = [&](int buf) {
        const uint32_t base = sbase + (uint32_t)buf * BUF_BYTES;
        const uint32_t pAh = base;
        const uint32_t pAl = base + A_BYTES;
        const uint32_t pBh = base + 2 * A_BYTES;
        const uint32_t pBl = base + 2 * A_BYTES + B_BYTES;
#pragma unroll
        for (int ks = 0; ks < 2; ks++) {
            const uint32_t kb = (uint32_t)ks * 32u;  // 16 bf16 = 32B
            uint32_t ah[4][4], al[4][4];
#pragma unroll
            for (int mi = 0; mi < 4; mi++)
                ldx4(ah[mi], pAh + aOff + kb + (uint32_t)mi * (16 * A_LD * 2));
#pragma unroll
            for (int mi = 0; mi < 4; mi++)
                ldx4(al[mi], pAl + aOff + kb + (uint32_t)mi * (16 * A_LD * 2));
#pragma unroll
            for (int ng = 0; ng < 4; ng++) {
                uint32_t b[4];
                ldx4(b, pBh + bOff + kb + (uint32_t)ng * (16 * B_LD * 2));
#pragma unroll
                for (int mi = 0; mi < 4; mi++) {
                    mma16816(acc[mi][2 * ng],     ah[mi], b[0], b[1]);
                    mma16816(acc[mi][2 * ng + 1], ah[mi], b[2], b[3]);
                }
#pragma unroll
                for (int mi = 0; mi < 4; mi++) {
                    mma16816(acc[mi][2 * ng],     al[mi], b[0], b[1]);
                    mma16816(acc[mi][2 * ng + 1], al[mi], b[2], b[3]);
                }
            }
#pragma unroll
            for (int ng = 0; ng < 4; ng++) {
                uint32_t b[4];
                ldx4(b, pBl + bOff + kb + (uint32_t)ng * (16 * B_LD * 2));
#pragma unroll
                for (int mi = 0; mi < 4; mi++) {
                    mma16816(acc[mi][2 * ng],     ah[mi], b[0], b[1]);
                    mma16816(acc[mi][2 * ng + 1], ah[mi], b[2], b[3]);
                }
            }
        }
    };

    // ---- pipeline ----
    loadG(0);
    storeS(0);
    loadG(BKI);
    __syncthreads();

    for (int it = 0; it < NIT; ++it) {
        compute(it & 1);
        if (it + 1 < NIT) {
            storeS((it + 1) & 1);      // buffer last read in compute(it-1); barrier guarantees done
            if (it + 2 < NIT) loadG((it + 2) * BKI);
            __syncthreads();
        }
    }

    // ---- epilogue ----
#pragma unroll
    for (int mi = 0; mi < 4; mi++) {
#pragma unroll
        for (int nb = 0; nb < 8; nb++) {
            int r = bm0 + wm * 64 + mi * 16 + (lane >> 2);
            int c = bn0 + wn * 64 + nb * 8 + (lane & 3) * 2;
            *reinterpret_cast<float2*>(y + (size_t)r * OUT_DIM + c) =
                make_float2(acc[mi][nb][0], acc[mi][nb][1]);
            *reinterpret_cast<float2*>(y + (size_t)(r + 8) * OUT_DIM + c) =
                make_float2(acc[mi][nb][2], acc[mi][nb][3]);
        }
    }
}

extern "C" void kernel_launch(void* const* d_in, const int* in_sizes, int n_in,
                              void* d_out, int out_size) {
    const float* x      = (const float*)d_in[0];
    const float* a_ptr  = (const float*)d_in[1];
    const float* q_ptr  = (const float*)d_in[2];
    const float* coeffs = (const float*)d_in[3];
    float* y = (float*)d_out;

    cudaFuncSetAttribute(kan_mma2_kernel, cudaFuncAttributeMaxDynamicSharedMemorySize, SMEM_DYN);
    dim3 grid(OUT_DIM / BN, BATCH / BM);  // (4, 32) = 128 CTAs, single wave
    kan_mma2_kernel<<<grid, THREADS, SMEM_DYN>>>(x, a_ptr, q_ptr, coeffs, y);
}

// round 6
// speedup vs baseline: 2.7155x; 1.0196x over previous
#include <cuda_runtime.h>
#include <cuda_bf16.h>
#include <cstdint>

// y[b,o] = sum_{i,d} P_d(tanh(x[b,i])) * coeffs[i,o,d]
// GEMM M=4096 N=1024 K=8192, A generated on the fly.
// mma.sync m16n8k16 bf16, split-bf16 3-pass (AhBh + AhBl + AlBh), fp32 accum.
// v6 (= v5 resubmit; round-5 bench was an infra failure):
// 128x256 CTA (1 wave), 16 warps x (32x64) tiles, double buffer, no spills.

#define BATCH   4096
#define IN_DIM  1024
#define OUT_DIM 1024
#define NB      8

#define BM 128
#define BN 256
#define BKI 4                  // i-values per iter
#define NIT (IN_DIM / BKI)     // 256
#define THREADS 512            // 16 warps, warp grid 4(M) x 4(N), warp tile 32x64

#define A_LD 40                // bf16 per row (80B stride, conflict-free, 16B aligned)
#define B_LD 40
#define A_BYTES (BM * A_LD * 2)                // 10240
#define B_BYTES (BN * B_LD * 2)                // 20480
#define BUF_BYTES (2 * A_BYTES + 2 * B_BYTES)  // 61440: Ah, Al, Bh, Bl
#define SMEM_DYN (2 * BUF_BYTES)               // 122880

__device__ __forceinline__ void ldx4(uint32_t* r, uint32_t addr) {
    asm volatile("ldmatrix.sync.aligned.m8n8.x4.shared.b16 {%0,%1,%2,%3}, [%4];"
                 : "=r"(r[0]), "=r"(r[1]), "=r"(r[2]), "=r"(r[3]) : "r"(addr));
}
__device__ __forceinline__ void mma16816(float* d, const uint32_t* a, uint32_t b0, uint32_t b1) {
    asm volatile("mma.sync.aligned.m16n8k16.row.col.f32.bf16.bf16.f32 "
                 "{%0,%1,%2,%3}, {%4,%5,%6,%7}, {%8,%9}, {%0,%1,%2,%3};"
                 : "+f"(d[0]), "+f"(d[1]), "+f"(d[2]), "+f"(d[3])
                 : "r"(a[0]), "r"(a[1]), "r"(a[2]), "r"(a[3]), "r"(b0), "r"(b1));
}
__device__ __forceinline__ uint32_t bf2u(__nv_bfloat162 v) {
    return *reinterpret_cast<uint32_t*>(&v);
}

__global__ __launch_bounds__(THREADS, 1)
void kan_mma3_kernel(const float* __restrict__ x,
                     const float* __restrict__ a_ptr,
                     const float* __restrict__ q_ptr,
                     const float* __restrict__ coeffs,
                     float* __restrict__ y) {
    extern __shared__ __align__(16) char sm[];
    const uint32_t sbase = (uint32_t)__cvta_generic_to_shared(sm);

    const float a = a_ptr[0];
    const float q = q_ptr[0];
    const int bn0 = blockIdx.x * BN;
    const int bm0 = blockIdx.y * BM;
    const int tid = threadIdx.x;
    const int lane = tid & 31;
    const int warp = tid >> 5;
    const int wm = warp >> 2;   // 0..3  (M groups of 32)
    const int wn = warp & 3;    // 0..3  (N groups of 64)

    // accumulators: [mi 0..1][n8 0..7][4]
    float acc[2][8][4];
#pragma unroll
    for (int mi = 0; mi < 2; mi++)
#pragma unroll
        for (int nb = 0; nb < 8; nb++)
#pragma unroll
            for (int r = 0; r < 4; r++) acc[mi][nb][r] = 0.0f;

    // ldmatrix lane offsets
    const int aRow = wm * 32 + (lane & 15);                      // + mi*16
    const uint32_t aOff = (uint32_t)(aRow * A_LD + (lane >> 4) * 8) * 2u;   // + ks*32B
    const int bRow = wn * 64 + ((lane >> 4) << 3) + (lane & 7);  // + ng*16
    const uint32_t bOff = (uint32_t)(bRow * B_LD + ((lane >> 3) & 1) * 8) * 2u;

    // register prefetch
    float4 pfB[4];
    float pfX;

    auto loadG = [&](int i0) {
#pragma unroll
        for (int jj = 0; jj < 4; jj++) {
            int t = tid + jj * THREADS;   // 0..2047
            int il = t >> 9;              // 0..3
            int f = t & 511;
            int n = f >> 1;
            int dh = f & 1;
            pfB[jj] = *reinterpret_cast<const float4*>(
                coeffs + (size_t)(i0 + il) * (OUT_DIM * NB) + (size_t)(bn0 + n) * NB + dh * 4);
        }
        {
            int il = tid & 3;
            int row = tid >> 2;
            pfX = x[(size_t)(bm0 + row) * IN_DIM + i0 + il];
        }
    };

    auto storeS = [&](int buf) {
        char* const base = sm + buf * BUF_BYTES;
        char* const Ah = base;
        char* const Al = base + A_BYTES;
        char* const Bh = base + 2 * A_BYTES;
        char* const Bl = base + 2 * A_BYTES + B_BYTES;

        // B: [n][k] layout, k = il*8 + d (d contiguous)
#pragma unroll
        for (int jj = 0; jj < 4; jj++) {
            int t = tid + jj * THREADS;
            int il = t >> 9;
            int f = t & 511;
            int n = f >> 1;
            int dh = f & 1;
            float v[4] = {pfB[jj].x, pfB[jj].y, pfB[jj].z, pfB[jj].w};
            __nv_bfloat162 h01 = __floats2bfloat162_rn(v[0], v[1]);
            __nv_bfloat162 h23 = __floats2bfloat162_rn(v[2], v[3]);
            __nv_bfloat162 l01 = __floats2bfloat162_rn(v[0] - __bfloat162float(h01.x),
                                                       v[1] - __bfloat162float(h01.y));
            __nv_bfloat162 l23 = __floats2bfloat162_rn(v[2] - __bfloat162float(h23.x),
                                                       v[3] - __bfloat162float(h23.y));
            uint32_t off = (uint32_t)(n * B_LD + il * 8 + dh * 4) * 2u;
            *reinterpret_cast<uint2*>(Bh + off) = make_uint2(bf2u(h01), bf2u(h23));
            *reinterpret_cast<uint2*>(Bl + off) = make_uint2(bf2u(l01), bf2u(l23));
        }

        // A: [m][k] layout, k = il*8 + d
        {
            int il = tid & 3;
            int row = tid >> 2;
            float xt = tanhf(pfX);
            float p[NB];
            p[0] = 1.0f;
            p[1] = xt - a;
            float qn = q;
#pragma unroll
            for (int n = 2; n < NB; n++) {
                float qn1 = qn * q;
                p[n] = (xt - (a + qn1)) * p[n - 1] - (a * qn) * p[n - 2];
                qn = qn1;
            }
            uint32_t hw[4], lw[4];
#pragma unroll
            for (int j = 0; j < 4; j++) {
                __nv_bfloat162 h = __floats2bfloat162_rn(p[2 * j], p[2 * j + 1]);
                __nv_bfloat162 l = __floats2bfloat162_rn(p[2 * j]     - __bfloat162float(h.x),
                                                         p[2 * j + 1] - __bfloat162float(h.y));
                hw[j] = bf2u(h);
                lw[j] = bf2u(l);
            }
            uint32_t off = (uint32_t)(row * A_LD + il * 8) * 2u;
            *reinterpret_cast<uint4*>(Ah + off) = make_uint4(hw[0], hw[1], hw[2], hw[3]);
            *reinterpret_cast<uint4*>(Al + off) = make_uint4(lw[0], lw[1], lw[2], lw[3]);
        }
    };

    auto compute = [&](int buf) {
        const uint32_t base = sbase + (uint32_t)buf * BUF_BYTES;
        const uint32_t pAh = base;
        const uint32_t pAl = base + A_BYTES;
        const uint32_t pBh = base + 2 * A_BYTES;
        const uint32_t pBl = base + 2 * A_BYTES + B_BYTES;
#pragma unroll
        for (int ks = 0; ks < 2; ks++) {
            const uint32_t kb = (uint32_t)ks * 32u;  // 16 bf16 = 32B
            uint32_t ah[2][4], al[2][4];
#pragma unroll
            for (int mi = 0; mi < 2; mi++)
                ldx4(ah[mi], pAh + aOff + kb + (uint32_t)mi * (16 * A_LD * 2));
#pragma unroll
            for (int mi = 0; mi < 2; mi++)
                ldx4(al[mi], pAl + aOff + kb + (uint32_t)mi * (16 * A_LD * 2));
#pragma unroll
            for (int ng = 0; ng < 4; ng++) {
                uint32_t bh[4], bl[4];
                ldx4(bh, pBh + bOff + kb + (uint32_t)ng * (16 * B_LD * 2));
                ldx4(bl, pBl + bOff + kb + (uint32_t)ng * (16 * B_LD * 2));
                // pass 1: Ah*Bh
#pragma unroll
                for (int mi = 0; mi < 2; mi++) {
                    mma16816(acc[mi][2 * ng],     ah[mi], bh[0], bh[1]);
                    mma16816(acc[mi][2 * ng + 1], ah[mi], bh[2], bh[3]);
                }
                // pass 2: Ah*Bl
#pragma unroll
                for (int mi = 0; mi < 2; mi++) {
                    mma16816(acc[mi][2 * ng],     ah[mi], bl[0], bl[1]);
                    mma16816(acc[mi][2 * ng + 1], ah[mi], bl[2], bl[3]);
                }
                // pass 3: Al*Bh
#pragma unroll
                for (int mi = 0; mi < 2; mi++) {
                    mma16816(acc[mi][2 * ng],     al[mi], bh[0], bh[1]);
                    mma16816(acc[mi][2 * ng + 1], al[mi], bh[2], bh[3]);
                }
            }
        }
    };

    // ---- pipeline ----
    loadG(0);
    storeS(0);
    loadG(BKI);
    __syncthreads();

    for (int it = 0; it < NIT; ++it) {
        compute(it & 1);
        if (it + 1 < NIT) {
            storeS((it + 1) & 1);
            if (it + 2 < NIT) loadG((it + 2) * BKI);
            __syncthreads();
        }
    }

    // ---- epilogue ----
#pragma unroll
    for (int mi = 0; mi < 2; mi++) {
#pragma unroll
        for (int nb = 0; nb < 8; nb++) {
            int r = bm0 + wm * 32 + mi * 16 + (lane >> 2);
            int c = bn0 + wn * 64 + nb * 8 + (lane & 3) * 2;
            *reinterpret_cast<float2*>(y + (size_t)r * OUT_DIM + c) =
                make_float2(acc[mi][nb][0], acc[mi][nb][1]);
            *reinterpret_cast<float2*>(y + (size_t)(r + 8) * OUT_DIM + c) =
                make_float2(acc[mi][nb][2], acc[mi][nb][3]);
        }
    }
}

extern "C" void kernel_launch(void* const* d_in, const int* in_sizes, int n_in,
                              void* d_out, int out_size) {
    const float* x      = (const float*)d_in[0];
    const float* a_ptr  = (const float*)d_in[1];
    const float* q_ptr  = (const float*)d_in[2];
    const float* coeffs = (const float*)d_in[3];
    float* y = (float*)d_out;

    cudaFuncSetAttribute(kan_mma3_kernel, cudaFuncAttributeMaxDynamicSharedMemorySize, SMEM_DYN);
    dim3 grid(OUT_DIM / BN, BATCH / BM);  // (4, 32) = 128 CTAs, single wave
    kan_mma3_kernel<<<grid, THREADS, SMEM_DYN>>>(x, a_ptr, q_ptr, coeffs, y);
}